// round 1
// baseline (speedup 1.0000x reference)
#include <cuda_runtime.h>
#include <cuda_bf16.h>
#include <mma.h>

using namespace nvcuda;

#define B_ 2
#define S_ 4096
#define E_ 1024
#define H_ 16
#define D_ 64
#define NTOK (B_*S_)
#define NELEM (NTOK*E_)

// Scratch (static device globals: no allocation in kernel_launch)
__device__ float g_q[NELEM];
__device__ float g_k[NELEM];
__device__ float g_v[NELEM];

// ---------------------------------------------------------------------------
// Projection GEMM: C = scale * (X @ W^T + bias)
// X: [8192, 1024] f32 row-major. W: [1024,1024] row-major [n][k].
// Bias fused as augmented K row (k==1024): A[:,1024]=1, B[n][1024]=bias[n].
// tf32 WMMA m16n16k8, fp32 accumulate. BM=128, BN=128, BK=16, 8 warps (4x2),
// each warp 32x64 (2x4 fragments).
// ---------------------------------------------------------------------------
#define GBM 128
#define GBN 128
#define GBK 16
#define GLD (GBK+4)   // 20 floats: pad, 16B-aligned rows

__global__ void __launch_bounds__(256) gemm_qkv(const float* __restrict__ X,
                                                const float* __restrict__ Wt,
                                                const float* __restrict__ bias,
                                                float scale, int which) {
    float* C = (which == 0) ? g_q : ((which == 1) ? g_k : g_v);
    __shared__ float As[GBM][GLD];
    __shared__ float Bs[GBN][GLD];

    const int m0 = blockIdx.y * GBM;
    const int n0 = blockIdx.x * GBN;
    const int tid = threadIdx.x;
    const int w = tid >> 5;
    const int wm = w >> 1;   // 0..3 -> 32 rows each
    const int wn = w & 1;    // 0..1 -> 64 cols each

    wmma::fragment<wmma::accumulator, 16, 16, 8, float> acc[2][4];
#pragma unroll
    for (int mm = 0; mm < 2; mm++)
#pragma unroll
        for (int nn = 0; nn < 4; nn++)
            wmma::fill_fragment(acc[mm][nn], 0.0f);

    for (int kt = 0; kt < 65; kt++) {
        const int kk0 = kt * 16;
        if (kk0 < 1024) {
#pragma unroll
            for (int r = 0; r < 2; r++) {
                int idx = tid + r * 256;
                int row = idx >> 2, c4 = idx & 3;
                float4 va = *(const float4*)(X + (size_t)(m0 + row) * 1024 + kk0 + c4 * 4);
                float4 ta;
                ta.x = wmma::__float_to_tf32(va.x);
                ta.y = wmma::__float_to_tf32(va.y);
                ta.z = wmma::__float_to_tf32(va.z);
                ta.w = wmma::__float_to_tf32(va.w);
                *(float4*)(&As[row][c4 * 4]) = ta;

                float4 vb = *(const float4*)(Wt + (size_t)(n0 + row) * 1024 + kk0 + c4 * 4);
                float4 tb;
                tb.x = wmma::__float_to_tf32(vb.x * scale);
                tb.y = wmma::__float_to_tf32(vb.y * scale);
                tb.z = wmma::__float_to_tf32(vb.z * scale);
                tb.w = wmma::__float_to_tf32(vb.w * scale);
                *(float4*)(&Bs[row][c4 * 4]) = tb;
            }
        } else {
            // tail tile: k = 1024..1039. A: k==1024 -> 1. B: k==1024 -> bias*scale.
#pragma unroll
            for (int r = 0; r < 2; r++) {
                int idx = tid + r * 256;
                int row = idx >> 2, c4 = idx & 3;
                float4 ta = make_float4(0.f, 0.f, 0.f, 0.f);
                float4 tb = make_float4(0.f, 0.f, 0.f, 0.f);
                if (c4 == 0) {
                    ta.x = 1.0f;
                    tb.x = wmma::__float_to_tf32(bias[n0 + row] * scale);
                }
                *(float4*)(&As[row][c4 * 4]) = ta;
                *(float4*)(&Bs[row][c4 * 4]) = tb;
            }
        }
        __syncthreads();

#pragma unroll
        for (int ks = 0; ks < 2; ks++) {
            wmma::fragment<wmma::matrix_a, 16, 16, 8, wmma::precision::tf32, wmma::row_major> af[2];
            wmma::fragment<wmma::matrix_b, 16, 16, 8, wmma::precision::tf32, wmma::col_major> bf[4];
#pragma unroll
            for (int mm = 0; mm < 2; mm++)
                wmma::load_matrix_sync(af[mm], &As[wm * 32 + mm * 16][ks * 8], GLD);
#pragma unroll
            for (int nn = 0; nn < 4; nn++)
                wmma::load_matrix_sync(bf[nn], &Bs[wn * 64 + nn * 16][ks * 8], GLD);
#pragma unroll
            for (int mm = 0; mm < 2; mm++)
#pragma unroll
                for (int nn = 0; nn < 4; nn++)
                    wmma::mma_sync(acc[mm][nn], af[mm], bf[nn], acc[mm][nn]);
        }
        __syncthreads();
    }

#pragma unroll
    for (int mm = 0; mm < 2; mm++)
#pragma unroll
        for (int nn = 0; nn < 4; nn++)
            wmma::store_matrix_sync(C + (size_t)(m0 + wm * 32 + mm * 16) * 1024
                                      + (n0 + wn * 64 + nn * 16),
                                    acc[mm][nn], 1024, wmma::mem_row_major);
}

// ---------------------------------------------------------------------------
// Banded flash attention, fp32. One block = (b, h, 64-query chunk).
// Key band for the chunk: [chunk0-256, chunk0+320) = 9 tiles of 64.
// 256 threads: thread owns 2 queries (qg = tid>>3) x 8 keys / 8 d's (kg = tid&7).
// Online softmax with shared m/l state.
// ---------------------------------------------------------------------------
#define ATTN_SMEM ((4*64*65 + 2*512 + 3*64) * 4)

__global__ void __launch_bounds__(256) attn_kernel(const int* __restrict__ am,
                                                   float* __restrict__ out) {
    extern __shared__ float sm[];
    float* Qs   = sm;             // [64][65]
    float* Ks   = Qs + 64 * 65;   // [64][65]
    float* Vs   = Ks + 64 * 65;   // [64][65]
    float* Sc   = Vs + 64 * 65;   // [64][65]
    float* redM = Sc + 64 * 65;   // [64][8]
    float* redL = redM + 512;     // [64][8]
    float* mS   = redL + 512;     // [64]
    float* lS   = mS + 64;        // [64]
    float* fmS  = lS + 64;        // [64]

    const int chunk0 = blockIdx.x * 64;
    const int h = blockIdx.y;
    const int b = blockIdx.z;
    const int tid = threadIdx.x;
    const int kg = tid & 7;       // key/d group of 8
    const int qg = tid >> 3;      // query pair 0..31
    const int q0 = qg * 2, q1 = q0 + 1;
    const size_t base = (size_t)b * S_ * E_ + h * 64;

#pragma unroll
    for (int r = 0; r < 4; r++) {
        int idx = tid + r * 256;
        int row = idx >> 4, c4 = idx & 15;
        float4 v = *(const float4*)(g_q + base + (size_t)(chunk0 + row) * E_ + c4 * 4);
        float* p = &Qs[row * 65 + c4 * 4];
        p[0] = v.x; p[1] = v.y; p[2] = v.z; p[3] = v.w;
    }
    if (tid < 64) { mS[tid] = -1e30f; lS[tid] = 0.f; }

    float o0[8], o1[8];
#pragma unroll
    for (int j = 0; j < 8; j++) { o0[j] = 0.f; o1[j] = 0.f; }

    for (int kt = 0; kt < 9; kt++) {
        const int kstart = chunk0 - 256 + kt * 64;
        if (kstart + 64 <= 0 || kstart >= S_) continue;
        __syncthreads();
#pragma unroll
        for (int r = 0; r < 4; r++) {
            int idx = tid + r * 256;
            int row = idx >> 4, c4 = idx & 15;
            int key = kstart + row;
            float4 kv = make_float4(0.f, 0.f, 0.f, 0.f);
            float4 vv = kv;
            if ((unsigned)key < (unsigned)S_) {
                size_t off = base + (size_t)key * E_ + c4 * 4;
                kv = *(const float4*)(g_k + off);
                vv = *(const float4*)(g_v + off);
            }
            float* pk = &Ks[row * 65 + c4 * 4];
            pk[0] = kv.x; pk[1] = kv.y; pk[2] = kv.z; pk[3] = kv.w;
            float* pv = &Vs[row * 65 + c4 * 4];
            pv[0] = vv.x; pv[1] = vv.y; pv[2] = vv.z; pv[3] = vv.w;
        }
        if (tid < 64) {
            int key = kstart + tid;
            fmS[tid] = ((unsigned)key < (unsigned)S_ && am[(size_t)b * S_ + key] != 0)
                           ? -10000.f : 0.f;
        }
        __syncthreads();

        float s0[8], s1[8];
#pragma unroll
        for (int j = 0; j < 8; j++) { s0[j] = 0.f; s1[j] = 0.f; }
        const float* qrow0 = &Qs[q0 * 65];
        const float* qrow1 = &Qs[q1 * 65];
#pragma unroll 8
        for (int d = 0; d < 64; d++) {
            float a0 = qrow0[d], a1 = qrow1[d];
#pragma unroll
            for (int j = 0; j < 8; j++) {
                float kvv = Ks[(kg * 8 + j) * 65 + d];
                s0[j] = fmaf(a0, kvv, s0[j]);
                s1[j] = fmaf(a1, kvv, s1[j]);
            }
        }
        const int qa = chunk0 + q0, qb2 = chunk0 + q1;
        float lm0 = -1e30f, lm1 = -1e30f;
#pragma unroll
        for (int j = 0; j < 8; j++) {
            int key = kstart + kg * 8 + j;
            bool inr = (unsigned)key < (unsigned)S_;
            float addv = fmS[kg * 8 + j];
            int r0 = key - qa, r1 = key - qb2;
            s0[j] = (inr && r0 >= -256 && r0 <= 256) ? s0[j] + addv : -1e30f;
            s1[j] = (inr && r1 >= -256 && r1 <= 256) ? s1[j] + addv : -1e30f;
            lm0 = fmaxf(lm0, s0[j]);
            lm1 = fmaxf(lm1, s1[j]);
        }
        redM[q0 * 8 + kg] = lm0;
        redM[q1 * 8 + kg] = lm1;
        __syncthreads();
        float mold0 = mS[q0], mold1 = mS[q1];
        float mn0 = mold0, mn1 = mold1;
#pragma unroll
        for (int g2 = 0; g2 < 8; g2++) {
            mn0 = fmaxf(mn0, redM[q0 * 8 + g2]);
            mn1 = fmaxf(mn1, redM[q1 * 8 + g2]);
        }
        float sc0 = __expf(mold0 - mn0), sc1 = __expf(mold1 - mn1);
        float ps0 = 0.f, ps1 = 0.f;
#pragma unroll
        for (int j = 0; j < 8; j++) {
            float p0 = __expf(s0[j] - mn0);
            float p1 = __expf(s1[j] - mn1);
            Sc[q0 * 65 + kg * 8 + j] = p0;
            Sc[q1 * 65 + kg * 8 + j] = p1;
            ps0 += p0; ps1 += p1;
        }
#pragma unroll
        for (int j = 0; j < 8; j++) { o0[j] *= sc0; o1[j] *= sc1; }
        redL[q0 * 8 + kg] = ps0;
        redL[q1 * 8 + kg] = ps1;
        __syncthreads();
        if (kg == 0) {
            float l0 = lS[q0] * sc0, l1 = lS[q1] * sc1;
#pragma unroll
            for (int g2 = 0; g2 < 8; g2++) { l0 += redL[q0 * 8 + g2]; l1 += redL[q1 * 8 + g2]; }
            lS[q0] = l0; lS[q1] = l1; mS[q0] = mn0; mS[q1] = mn1;
        }
        const float* sr0 = &Sc[q0 * 65];
        const float* sr1 = &Sc[q1 * 65];
#pragma unroll 4
        for (int kk = 0; kk < 64; kk++) {
            float p0 = sr0[kk], p1 = sr1[kk];
#pragma unroll
            for (int j = 0; j < 8; j++) {
                float vvv = Vs[kk * 65 + kg * 8 + j];
                o0[j] = fmaf(p0, vvv, o0[j]);
                o1[j] = fmaf(p1, vvv, o1[j]);
            }
        }
    }
    __syncthreads();
    float inv0 = 1.f / lS[q0];
    float inv1 = 1.f / lS[q1];
    size_t ob0 = base + (size_t)(chunk0 + q0) * E_ + kg * 8;
    size_t ob1 = base + (size_t)(chunk0 + q1) * E_ + kg * 8;
    float4 a = make_float4(o0[0] * inv0, o0[1] * inv0, o0[2] * inv0, o0[3] * inv0);
    float4 c = make_float4(o0[4] * inv0, o0[5] * inv0, o0[6] * inv0, o0[7] * inv0);
    *(float4*)(out + ob0) = a;
    *(float4*)(out + ob0 + 4) = c;
    float4 e = make_float4(o1[0] * inv1, o1[1] * inv1, o1[2] * inv1, o1[3] * inv1);
    float4 f = make_float4(o1[4] * inv1, o1[5] * inv1, o1[6] * inv1, o1[7] * inv1);
    *(float4*)(out + ob1) = e;
    *(float4*)(out + ob1 + 4) = f;
}

// ---------------------------------------------------------------------------
extern "C" void kernel_launch(void* const* d_in, const int* in_sizes, int n_in,
                              void* d_out, int out_size) {
    const float* hs = (const float*)d_in[0];
    const int*   am = (const int*)d_in[1];
    const float* qw = (const float*)d_in[2];
    const float* qb = (const float*)d_in[3];
    const float* kw = (const float*)d_in[4];
    const float* kb = (const float*)d_in[5];
    const float* vw = (const float*)d_in[6];
    const float* vb = (const float*)d_in[7];
    float* out = (float*)d_out;

    dim3 gg(E_ / GBN, NTOK / GBM);
    gemm_qkv<<<gg, 256>>>(hs, qw, qb, 0.125f, 0);   // Q: (xW^T+b)/sqrt(64)
    gemm_qkv<<<gg, 256>>>(hs, kw, kb, 1.0f, 1);
    gemm_qkv<<<gg, 256>>>(hs, vw, vb, 1.0f, 2);

    cudaFuncSetAttribute(attn_kernel, cudaFuncAttributeMaxDynamicSharedMemorySize, ATTN_SMEM);
    dim3 ga(S_ / 64, H_, B_);
    attn_kernel<<<ga, 256, ATTN_SMEM>>>(am, out);
}

// round 2
// speedup vs baseline: 2.0350x; 2.0350x over previous
#include <cuda_runtime.h>
#include <cuda_bf16.h>
#include <mma.h>

using namespace nvcuda;

#define B_ 2
#define S_ 4096
#define E_ 1024
#define H_ 16
#define D_ 64
#define NTOK (B_*S_)
#define NELEM (NTOK*E_)

__device__ float g_q[NELEM];
__device__ float g_k[NELEM];
__device__ float g_v[NELEM];

// ---------------------------------------------------------------------------
// Projection GEMM: C = scale * (X @ W^T + bias), bias fused as augmented K row.
// tf32 WMMA m16n16k8. One launch, blockIdx.z selects Q/K/V.
// ---------------------------------------------------------------------------
#define GBM 128
#define GBN 128
#define GLD 20

__global__ void __launch_bounds__(256) gemm_qkv(const float* __restrict__ X,
                                                const float* __restrict__ qw, const float* __restrict__ qb,
                                                const float* __restrict__ kw, const float* __restrict__ kb,
                                                const float* __restrict__ vw, const float* __restrict__ vb) {
    const int which = blockIdx.z;
    const float* Wt  = (which == 0) ? qw : ((which == 1) ? kw : vw);
    const float* bias= (which == 0) ? qb : ((which == 1) ? kb : vb);
    const float scale = (which == 0) ? 0.125f : 1.0f;
    float* C = (which == 0) ? g_q : ((which == 1) ? g_k : g_v);

    __shared__ float As[GBM][GLD];
    __shared__ float Bs[GBN][GLD];

    const int m0 = blockIdx.y * GBM;
    const int n0 = blockIdx.x * GBN;
    const int tid = threadIdx.x;
    const int w = tid >> 5;
    const int wm = w >> 1;
    const int wn = w & 1;

    wmma::fragment<wmma::accumulator, 16, 16, 8, float> acc[2][4];
#pragma unroll
    for (int mm = 0; mm < 2; mm++)
#pragma unroll
        for (int nn = 0; nn < 4; nn++)
            wmma::fill_fragment(acc[mm][nn], 0.0f);

    for (int kt = 0; kt < 65; kt++) {
        const int kk0 = kt * 16;
        if (kk0 < 1024) {
#pragma unroll
            for (int r = 0; r < 2; r++) {
                int idx = tid + r * 256;
                int row = idx >> 2, c4 = idx & 3;
                float4 va = *(const float4*)(X + (size_t)(m0 + row) * 1024 + kk0 + c4 * 4);
                float4 ta;
                ta.x = wmma::__float_to_tf32(va.x);
                ta.y = wmma::__float_to_tf32(va.y);
                ta.z = wmma::__float_to_tf32(va.z);
                ta.w = wmma::__float_to_tf32(va.w);
                *(float4*)(&As[row][c4 * 4]) = ta;

                float4 vb4 = *(const float4*)(Wt + (size_t)(n0 + row) * 1024 + kk0 + c4 * 4);
                float4 tb;
                tb.x = wmma::__float_to_tf32(vb4.x * scale);
                tb.y = wmma::__float_to_tf32(vb4.y * scale);
                tb.z = wmma::__float_to_tf32(vb4.z * scale);
                tb.w = wmma::__float_to_tf32(vb4.w * scale);
                *(float4*)(&Bs[row][c4 * 4]) = tb;
            }
        } else {
#pragma unroll
            for (int r = 0; r < 2; r++) {
                int idx = tid + r * 256;
                int row = idx >> 2, c4 = idx & 3;
                float4 ta = make_float4(0.f, 0.f, 0.f, 0.f);
                float4 tb = make_float4(0.f, 0.f, 0.f, 0.f);
                if (c4 == 0) {
                    ta.x = 1.0f;
                    tb.x = wmma::__float_to_tf32(bias[n0 + row] * scale);
                }
                *(float4*)(&As[row][c4 * 4]) = ta;
                *(float4*)(&Bs[row][c4 * 4]) = tb;
            }
        }
        __syncthreads();

#pragma unroll
        for (int ks = 0; ks < 2; ks++) {
            wmma::fragment<wmma::matrix_a, 16, 16, 8, wmma::precision::tf32, wmma::row_major> af[2];
            wmma::fragment<wmma::matrix_b, 16, 16, 8, wmma::precision::tf32, wmma::col_major> bf[4];
#pragma unroll
            for (int mm = 0; mm < 2; mm++)
                wmma::load_matrix_sync(af[mm], &As[wm * 32 + mm * 16][ks * 8], GLD);
#pragma unroll
            for (int nn = 0; nn < 4; nn++)
                wmma::load_matrix_sync(bf[nn], &Bs[wn * 64 + nn * 16][ks * 8], GLD);
#pragma unroll
            for (int mm = 0; mm < 2; mm++)
#pragma unroll
                for (int nn = 0; nn < 4; nn++)
                    wmma::mma_sync(acc[mm][nn], af[mm], bf[nn], acc[mm][nn]);
        }
        __syncthreads();
    }

#pragma unroll
    for (int mm = 0; mm < 2; mm++)
#pragma unroll
        for (int nn = 0; nn < 4; nn++)
            wmma::store_matrix_sync(C + (size_t)(m0 + wm * 32 + mm * 16) * 1024
                                      + (n0 + wn * 64 + nn * 16),
                                    acc[mm][nn], 1024, wmma::mem_row_major);
}

// ---------------------------------------------------------------------------
// Banded attention with WMMA tensor cores.
// One block = (64 queries, one (b,h)). 9 key tiles of 64 in the ±256 band.
// No running max / no rescale: scores are O(1), masked entries use -1e4
// (expf underflows to exact 0), so O accumulates in WMMA fragments across
// all tiles; only an elementwise exp pass between QK^T and PV.
// ---------------------------------------------------------------------------
#define AP 72
#define ATTN_SMEM ((4*64*AP + 64 + 256) * 4)

__global__ void __launch_bounds__(256) attn_wmma(const int* __restrict__ am,
                                                 float* __restrict__ out) {
    extern __shared__ float sm[];
    float* Qs = sm;                 // [64][AP] tf32
    float* Ks = Qs + 64 * AP;       // [64][AP] tf32
    float* Vs = Ks + 64 * AP;       // [64][AP] tf32
    float* Ps = Vs + 64 * AP;       // [64][AP] scores -> P(tf32) -> O
    float* fmS  = Ps + 64 * AP;     // [64]
    float* lred = fmS + 64;         // [64][4]

    const int chunk0 = blockIdx.x * 64;
    const int h = blockIdx.y;
    const int b = blockIdx.z;
    const int tid = threadIdx.x;
    const int warp = tid >> 5;
    const int tm = warp >> 1;           // output tile row 0..3
    const int tn2 = (warp & 1) * 2;     // output tile cols {tn2, tn2+1}
    const int rr = tid >> 2;            // exp-pass row 0..63
    const int cq = tid & 3;             // exp-pass col quarter

    const size_t base = (size_t)b * S_ * E_ + h * 64;

    // Load Q tile (tf32)
#pragma unroll
    for (int r = 0; r < 4; r++) {
        int idx = tid + r * 256;
        int row = idx >> 4, c4 = idx & 15;
        float4 v = *(const float4*)(g_q + base + (size_t)(chunk0 + row) * E_ + c4 * 4);
        float4 t;
        t.x = wmma::__float_to_tf32(v.x);
        t.y = wmma::__float_to_tf32(v.y);
        t.z = wmma::__float_to_tf32(v.z);
        t.w = wmma::__float_to_tf32(v.w);
        *(float4*)(&Qs[row * AP + c4 * 4]) = t;
    }

    wmma::fragment<wmma::accumulator, 16, 16, 8, float> oacc[2];
    wmma::fill_fragment(oacc[0], 0.0f);
    wmma::fill_fragment(oacc[1], 0.0f);
    float lpart = 0.0f;

    for (int kt = 0; kt < 9; kt++) {
        const int kstart = chunk0 - 256 + kt * 64;
        if (kstart < 0 || kstart >= S_) continue;   // tiles are fully in or out
        __syncthreads();
        // Load K,V tiles (tf32)
#pragma unroll
        for (int r = 0; r < 4; r++) {
            int idx = tid + r * 256;
            int row = idx >> 4, c4 = idx & 15;
            size_t off = base + (size_t)(kstart + row) * E_ + c4 * 4;
            float4 kv = *(const float4*)(g_k + off);
            float4 vv = *(const float4*)(g_v + off);
            float4 tk, tv;
            tk.x = wmma::__float_to_tf32(kv.x); tk.y = wmma::__float_to_tf32(kv.y);
            tk.z = wmma::__float_to_tf32(kv.z); tk.w = wmma::__float_to_tf32(kv.w);
            tv.x = wmma::__float_to_tf32(vv.x); tv.y = wmma::__float_to_tf32(vv.y);
            tv.z = wmma::__float_to_tf32(vv.z); tv.w = wmma::__float_to_tf32(vv.w);
            *(float4*)(&Ks[row * AP + c4 * 4]) = tk;
            *(float4*)(&Vs[row * AP + c4 * 4]) = tv;
        }
        if (tid < 64) {
            int key = kstart + tid;
            fmS[tid] = (am[(size_t)b * S_ + key] != 0) ? -10000.f : 0.f;
        }
        __syncthreads();

        // S = Q @ K^T  (warp: tiles (tm,tn2), (tm,tn2+1))
        wmma::fragment<wmma::accumulator, 16, 16, 8, float> sacc[2];
        wmma::fill_fragment(sacc[0], 0.0f);
        wmma::fill_fragment(sacc[1], 0.0f);
#pragma unroll
        for (int ks = 0; ks < 8; ks++) {
            wmma::fragment<wmma::matrix_a, 16, 16, 8, wmma::precision::tf32, wmma::row_major> af;
            wmma::fragment<wmma::matrix_b, 16, 16, 8, wmma::precision::tf32, wmma::col_major> bf0, bf1;
            wmma::load_matrix_sync(af, &Qs[tm * 16 * AP + ks * 8], AP);
            wmma::load_matrix_sync(bf0, &Ks[tn2 * 16 * AP + ks * 8], AP);
            wmma::load_matrix_sync(bf1, &Ks[(tn2 + 1) * 16 * AP + ks * 8], AP);
            wmma::mma_sync(sacc[0], af, bf0, sacc[0]);
            wmma::mma_sync(sacc[1], af, bf1, sacc[1]);
        }
        wmma::store_matrix_sync(&Ps[tm * 16 * AP + tn2 * 16], sacc[0], AP, wmma::mem_row_major);
        wmma::store_matrix_sync(&Ps[tm * 16 * AP + (tn2 + 1) * 16], sacc[1], AP, wmma::mem_row_major);
        __syncthreads();

        // exp + mask pass: thread handles row rr, 16 cols at cq*16
        {
            const bool lower = (kt == 0);   // valid iff y >= rr
            const bool upper = (kt == 8);   // valid iff y <= rr
            float* prow = &Ps[rr * AP + cq * 16];
            float sum = 0.f;
#pragma unroll
            for (int j = 0; j < 16; j++) {
                int y = cq * 16 + j;
                float s = prow[j] + fmS[y];
                bool ok = (!lower || y >= rr) && (!upper || y <= rr);
                float p = ok ? __expf(s) : 0.f;
                sum += p;
                prow[j] = wmma::__float_to_tf32(p);
            }
            lpart += sum;
        }
        __syncthreads();

        // O += P @ V
#pragma unroll
        for (int ks = 0; ks < 8; ks++) {
            wmma::fragment<wmma::matrix_a, 16, 16, 8, wmma::precision::tf32, wmma::row_major> af;
            wmma::fragment<wmma::matrix_b, 16, 16, 8, wmma::precision::tf32, wmma::row_major> bf0, bf1;
            wmma::load_matrix_sync(af, &Ps[tm * 16 * AP + ks * 8], AP);
            wmma::load_matrix_sync(bf0, &Vs[ks * 8 * AP + tn2 * 16], AP);
            wmma::load_matrix_sync(bf1, &Vs[ks * 8 * AP + (tn2 + 1) * 16], AP);
            wmma::mma_sync(oacc[0], af, bf0, oacc[0]);
            wmma::mma_sync(oacc[1], af, bf1, oacc[1]);
        }
    }

    lred[rr * 4 + cq] = lpart;
    __syncthreads();
    // Dump O into Ps
    wmma::store_matrix_sync(&Ps[tm * 16 * AP + tn2 * 16], oacc[0], AP, wmma::mem_row_major);
    wmma::store_matrix_sync(&Ps[tm * 16 * AP + (tn2 + 1) * 16], oacc[1], AP, wmma::mem_row_major);
    __syncthreads();

    const float l = lred[rr * 4 + 0] + lred[rr * 4 + 1] + lred[rr * 4 + 2] + lred[rr * 4 + 3];
    const float inv = 1.0f / l;
    size_t ob = base + (size_t)(chunk0 + rr) * E_ + cq * 16;
#pragma unroll
    for (int c4 = 0; c4 < 4; c4++) {
        float* p = &Ps[rr * AP + cq * 16 + c4 * 4];
        float4 v = make_float4(p[0] * inv, p[1] * inv, p[2] * inv, p[3] * inv);
        *(float4*)(out + ob + c4 * 4) = v;
    }
}

// ---------------------------------------------------------------------------
extern "C" void kernel_launch(void* const* d_in, const int* in_sizes, int n_in,
                              void* d_out, int out_size) {
    const float* hs = (const float*)d_in[0];
    const int*   am = (const int*)d_in[1];
    const float* qw = (const float*)d_in[2];
    const float* qb = (const float*)d_in[3];
    const float* kw = (const float*)d_in[4];
    const float* kb = (const float*)d_in[5];
    const float* vw = (const float*)d_in[6];
    const float* vb = (const float*)d_in[7];
    float* out = (float*)d_out;

    dim3 gg(E_ / GBN, NTOK / GBM, 3);
    gemm_qkv<<<gg, 256>>>(hs, qw, qb, kw, kb, vw, vb);

    cudaFuncSetAttribute(attn_wmma, cudaFuncAttributeMaxDynamicSharedMemorySize, ATTN_SMEM);
    dim3 ga(S_ / 64, H_, B_);
    attn_wmma<<<ga, 256, ATTN_SMEM>>>(am, out);
}